// round 6
// baseline (speedup 1.0000x reference)
#include <cuda_runtime.h>

// Problem constants (fixed by the dataset): N=200000, E=6400000, F: 128 -> 8 -> 16
#define NMAX 200000
#define EMAX 6400000

// Scratch (no cudaMalloc allowed)
__device__ int   g_cnt[NMAX];        // edge in-degree (no self loop)
__device__ int   g_pre[NMAX];        // within-block exclusive prefix
__device__ int   g_cur[NMAX];        // CSR fill cursor; after fill = row_end
__device__ int   g_bsum[1024];       // per-block sums for scan
__device__ int   g_csr[EMAX];        // CSR src lists grouped by dst
__device__ float g_dis[NMAX];        // (1+deg)^-1/2
__device__ float g_h[NMAX * 8];      // (x @ W1) * dis[src]   (pre-scaled)
__device__ float g_r[NMAX * 8];      // relu-layer output * dis[src] (pre-scaled)
__device__ int   g_is64;             // edge_index dtype flag

// ---------------------------------------------------------------------------
// K0: detect whether edge_index is int64 or int32.
__global__ void k_detect(const void* ei, int N) {
    if (threadIdx.x == 0 && blockIdx.x == 0) {
        const long long* p = (const long long*)ei;
        int is64 = 1;
#pragma unroll
        for (int i = 0; i < 8; i++) {
            long long v = p[i];
            if (v < 0 || v >= (long long)N) is64 = 0;
        }
        g_is64 = is64;
    }
}

__global__ void k_zero(int N) {
    int i = blockIdx.x * blockDim.x + threadIdx.x;
    if (i < N) g_cnt[i] = 0;
}

// ---------------------------------------------------------------------------
// K1: degree count over dst half of edge_index (2 edges/thread).
__global__ void k_count(const void* ei, int E) {
    int t = blockIdx.x * blockDim.x + threadIdx.x;
    int e = t * 2;
    if (e >= E) return;
    int is64 = g_is64;
    int d0, d1 = -1;
    bool has1 = (e + 1 < E);
    if (is64) {
        const long long* p = (const long long*)ei + E + e;
        d0 = (int)p[0];
        if (has1) d1 = (int)p[1];
    } else {
        const int* p = (const int*)ei + E + e;
        d0 = p[0];
        if (has1) d1 = p[1];
    }
    atomicAdd(&g_cnt[d0], 1);
    if (has1) atomicAdd(&g_cnt[d1], 1);
}

// ---------------------------------------------------------------------------
// Exclusive scan of g_cnt -> g_cur (3 kernels; nb = ceil(N/256) <= 1024).
__global__ void k_scan1(int N) {
    __shared__ int sd[256];
    int i = blockIdx.x * 256 + threadIdx.x;
    int v = (i < N) ? g_cnt[i] : 0;
    sd[threadIdx.x] = v;
    __syncthreads();
    for (int off = 1; off < 256; off <<= 1) {
        int t = (threadIdx.x >= off) ? sd[threadIdx.x - off] : 0;
        __syncthreads();
        sd[threadIdx.x] += t;
        __syncthreads();
    }
    if (i < N) g_pre[i] = sd[threadIdx.x] - v;   // exclusive within block
    if (threadIdx.x == 255) g_bsum[blockIdx.x] = sd[255];
}

__global__ void k_scan2(int nb) {
    __shared__ int sd[1024];
    int tid = threadIdx.x;
    int v = (tid < nb) ? g_bsum[tid] : 0;
    sd[tid] = v;
    __syncthreads();
    for (int off = 1; off < 1024; off <<= 1) {
        int t = (tid >= off) ? sd[tid - off] : 0;
        __syncthreads();
        sd[tid] += t;
        __syncthreads();
    }
    if (tid < nb) g_bsum[tid] = sd[tid] - v;     // exclusive block offsets
}

__global__ void k_scan3(int N) {
    int i = blockIdx.x * 256 + threadIdx.x;
    if (i < N) g_cur[i] = g_pre[i] + g_bsum[blockIdx.x];
}

// ---------------------------------------------------------------------------
// K2: CSR fill: for each edge, g_csr[cursor(dst)++] = src. (2 edges/thread)
__global__ void k_fill(const void* ei, int E) {
    int t = blockIdx.x * blockDim.x + threadIdx.x;
    int e = t * 2;
    if (e >= E) return;
    int is64 = g_is64;
    int s0, d0, s1 = 0, d1 = 0;
    bool has1 = (e + 1 < E);
    if (is64) {
        const long long* ps = (const long long*)ei + e;
        const long long* pd = (const long long*)ei + E + e;
        s0 = (int)ps[0]; d0 = (int)pd[0];
        if (has1) { s1 = (int)ps[1]; d1 = (int)pd[1]; }
    } else {
        const int* ps = (const int*)ei + e;
        const int* pd = (const int*)ei + E + e;
        s0 = ps[0]; d0 = pd[0];
        if (has1) { s1 = ps[1]; d1 = pd[1]; }
    }
    int p0 = atomicAdd(&g_cur[d0], 1);
    g_csr[p0] = s0;
    if (has1) {
        int p1 = atomicAdd(&g_cur[d1], 1);
        g_csr[p1] = s1;
    }
}

// ---------------------------------------------------------------------------
// K3: h_scaled = (x @ W1) * dis. Warp per 2 nodes, grid-stride. W in regs.
// Also computes dis = rsqrt(1 + cnt) once.
__global__ void k_gemm1(const float* __restrict__ x, const float* __restrict__ W1, int N) {
    int lane = threadIdx.x & 31;
    int cg   = lane >> 2;
    int fp   = lane & 3;

    float2 w2[16];
#pragma unroll
    for (int c = 0; c < 16; c++)
        w2[c] = *(const float2*)&W1[(cg * 16 + c) * 8 + fp * 2];

    int warp  = (blockIdx.x * blockDim.x + threadIdx.x) >> 5;
    int nwarp = (gridDim.x * blockDim.x) >> 5;

    for (int n0 = warp * 2; n0 < N; n0 += nwarp * 2) {
        int n1 = n0 + 1;
        bool has1 = (n1 < N);

        const float4* xr0 = (const float4*)(x + (long long)n0 * 128);
        const float4* xr1 = (const float4*)(x + (long long)(has1 ? n1 : n0) * 128);

        float4 xa[4], xb[4];
#pragma unroll
        for (int i = 0; i < 4; i++) xa[i] = xr0[cg * 4 + i];
#pragma unroll
        for (int i = 0; i < 4; i++) xb[i] = xr1[cg * 4 + i];

        float a0 = 0.f, a1 = 0.f, b0 = 0.f, b1 = 0.f;
#pragma unroll
        for (int i = 0; i < 4; i++) {
            float2 wa = w2[i * 4 + 0], wb = w2[i * 4 + 1];
            float2 wc = w2[i * 4 + 2], wd = w2[i * 4 + 3];
            a0 = fmaf(xa[i].x, wa.x, a0); a1 = fmaf(xa[i].x, wa.y, a1);
            a0 = fmaf(xa[i].y, wb.x, a0); a1 = fmaf(xa[i].y, wb.y, a1);
            a0 = fmaf(xa[i].z, wc.x, a0); a1 = fmaf(xa[i].z, wc.y, a1);
            a0 = fmaf(xa[i].w, wd.x, a0); a1 = fmaf(xa[i].w, wd.y, a1);
            b0 = fmaf(xb[i].x, wa.x, b0); b1 = fmaf(xb[i].x, wa.y, b1);
            b0 = fmaf(xb[i].y, wb.x, b0); b1 = fmaf(xb[i].y, wb.y, b1);
            b0 = fmaf(xb[i].z, wc.x, b0); b1 = fmaf(xb[i].z, wc.y, b1);
            b0 = fmaf(xb[i].w, wd.x, b0); b1 = fmaf(xb[i].w, wd.y, b1);
        }
#pragma unroll
        for (int off = 16; off >= 4; off >>= 1) {
            a0 += __shfl_xor_sync(0xffffffffu, a0, off);
            a1 += __shfl_xor_sync(0xffffffffu, a1, off);
            b0 += __shfl_xor_sync(0xffffffffu, b0, off);
            b1 += __shfl_xor_sync(0xffffffffu, b1, off);
        }

        float r = 0.0f;
        if (lane < 2) {
            int nn = n0 + lane;
            if (nn < N) {
                r = rsqrtf(1.0f + (float)g_cnt[nn]);
                g_dis[nn] = r;
            }
        }
        float r0 = __shfl_sync(0xffffffffu, r, 0);
        float r1 = __shfl_sync(0xffffffffu, r, 1);

        if (lane < 4) {
            *(float2*)&g_h[(long long)n0 * 8 + fp * 2] = make_float2(a0 * r0, a1 * r0);
            if (has1)
                *(float2*)&g_h[(long long)n1 * 8 + fp * 2] = make_float2(b0 * r1, b1 * r1);
        }
    }
}

// ---------------------------------------------------------------------------
// K4: layer-1 aggregation as GATHER. Warp per node (grid-stride).
// lane = (ng = lane>>3 in [0,4), fl = lane&7): 8 lanes share one 32B h-row
// sector per neighbor -> coalesced. Fused: +self, *dis, +b1, relu, *dis.
__global__ void k_agg1(const float* __restrict__ b1, int N) {
    int lane = threadIdx.x & 31;
    int fl = lane & 7;
    int ng = lane >> 3;
    float bias = __ldg(&b1[fl]);

    int warp  = (blockIdx.x * blockDim.x + threadIdx.x) >> 5;
    int nwarp = (gridDim.x * blockDim.x) >> 5;

    for (int n = warp; n < N; n += nwarp) {
        int cnt   = g_cnt[n];
        int start = g_cur[n] - cnt;   // fill advanced cursor to row_end
        float acc0 = 0.f, acc1 = 0.f;
        int k = ng;
        for (; k + 4 < cnt; k += 8) {
            int s0 = g_csr[start + k];
            int s1 = g_csr[start + k + 4];
            acc0 += g_h[(long long)s0 * 8 + fl];
            acc1 += g_h[(long long)s1 * 8 + fl];
        }
        if (k < cnt) {
            int s0 = g_csr[start + k];
            acc0 += g_h[(long long)s0 * 8 + fl];
        }
        float acc = acc0 + acc1;
        acc += __shfl_xor_sync(0xffffffffu, acc, 16);
        acc += __shfl_xor_sync(0xffffffffu, acc, 8);

        if (lane < 8) {
            float dis  = g_dis[n];
            float self = g_h[(long long)n * 8 + fl];
            float v = fmaxf(fmaf(acc + self, dis, bias), 0.0f) * dis;
            g_r[(long long)n * 8 + fl] = v;
        }
    }
}

// ---------------------------------------------------------------------------
// K5: layer-2 aggregation as GATHER + W2 + b2 fused. Warp per node.
// W2 column j (j = lane&15) preloaded into 8 registers; 8-shfl broadcast.
__global__ void k_agg2(const float* __restrict__ W2, const float* __restrict__ b2,
                       float* __restrict__ out, int N) {
    int lane = threadIdx.x & 31;
    int fl = lane & 7;
    int ng = lane >> 3;
    int j  = lane & 15;

    float w[8];
#pragma unroll
    for (int f = 0; f < 8; f++) w[f] = __ldg(&W2[f * 16 + j]);
    float bb = __ldg(&b2[j]);

    int warp  = (blockIdx.x * blockDim.x + threadIdx.x) >> 5;
    int nwarp = (gridDim.x * blockDim.x) >> 5;

    for (int n = warp; n < N; n += nwarp) {
        int cnt   = g_cnt[n];
        int start = g_cur[n] - cnt;
        float acc0 = 0.f, acc1 = 0.f;
        int k = ng;
        for (; k + 4 < cnt; k += 8) {
            int s0 = g_csr[start + k];
            int s1 = g_csr[start + k + 4];
            acc0 += g_r[(long long)s0 * 8 + fl];
            acc1 += g_r[(long long)s1 * 8 + fl];
        }
        if (k < cnt) {
            int s0 = g_csr[start + k];
            acc0 += g_r[(long long)s0 * 8 + fl];
        }
        float acc = acc0 + acc1;
        acc += __shfl_xor_sync(0xffffffffu, acc, 16);
        acc += __shfl_xor_sync(0xffffffffu, acc, 8);

        // every lane now has the fl-sum; add self and scale by dis
        float self = g_r[(long long)n * 8 + fl];
        float dis  = g_dis[n];
        float total = (acc + self) * dis;

        float o = bb;
#pragma unroll
        for (int f = 0; f < 8; f++) {
            float af = __shfl_sync(0xffffffffu, total, f);  // lane f holds fl=f
            o = fmaf(af, w[f], o);
        }
        if (lane < 16) out[(long long)n * 16 + j] = o;
    }
}

// ---------------------------------------------------------------------------
extern "C" void kernel_launch(void* const* d_in, const int* in_sizes, int n_in,
                              void* d_out, int out_size) {
    const float* x   = (const float*)d_in[0];
    const void*  ei  = d_in[1];
    const float* W1  = (const float*)d_in[2];
    const float* b1  = (const float*)d_in[3];
    const float* W2  = (const float*)d_in[4];
    const float* b2  = (const float*)d_in[5];
    float* out = (float*)d_out;

    int N = in_sizes[0] / 128;
    int E = in_sizes[1] / 2;

    const int T = 256;
    int nb_N  = (N + T - 1) / T;          // also the scan block count (<=1024)
    int nb_E2 = ((E + 1) / 2 + T - 1) / T;

    k_detect<<<1, 32>>>(ei, N);
    k_zero<<<nb_N, T>>>(N);
    k_count<<<nb_E2, T>>>(ei, E);
    k_scan1<<<nb_N, T>>>(N);
    k_scan2<<<1, 1024>>>(nb_N);
    k_scan3<<<nb_N, T>>>(N);
    k_fill<<<nb_E2, T>>>(ei, E);
    k_gemm1<<<1184, T>>>(x, W1, N);
    k_agg1<<<2368, T>>>(b1, N);
    k_agg2<<<2368, T>>>(W2, b2, out, N);
}

// round 10
// speedup vs baseline: 1.3104x; 1.3104x over previous
#include <cuda_runtime.h>

// Problem constants (fixed by the dataset): N=200000, E=6400000, F: 128 -> 8 -> 16
#define NMAX 200000
#define EMAX 6400000

// Scratch (no cudaMalloc allowed)
__device__ float g_deg[NMAX];         // degree (float counts)
__device__ float g_dis[NMAX];         // deg^-1/2
__device__ float g_h[NMAX * 8];       // x@W1 (raw), then *dis[src] after k_scale
__device__ float g_agg[NMAX * 8];     // layer-1 unweighted aggregation
__device__ float g_r[NMAX * 8];       // relu(...)*dis[src] (pre-scaled)
__device__ float g_agg2[NMAX * 8];    // layer-2 unweighted aggregation
__device__ int2  g_edge[EMAX];        // packed (src, dst) int32
__device__ int   g_is64;              // edge_index dtype flag

#define NB_CONV 6250                  // E/(4*256) convert-role blocks
#define NB_GEMM 1184                  // gemm-role blocks (grid-stride)

// ---------------------------------------------------------------------------
// K0: detect whether edge_index is int64 or int32.
__global__ void k_detect(const void* ei, int N) {
    if (threadIdx.x == 0 && blockIdx.x == 0) {
        const long long* p = (const long long*)ei;
        int is64 = 1;
#pragma unroll
        for (int i = 0; i < 8; i++) {
            long long v = p[i];
            if (v < 0 || v >= (long long)N) is64 = 0;
        }
        g_is64 = is64;
    }
}

__global__ void k_init(int N) {
    int i = blockIdx.x * blockDim.x + threadIdx.x;
    if (i < N) g_deg[i] = 1.0f;   // self-loop
}

// ---------------------------------------------------------------------------
// K1 (fused): role-split kernel.
//  blocks [0, NB_CONV): convert edge_index -> packed int2 (4 edges/thread)
//                       + degree atomics.
//  blocks [NB_CONV, +NB_GEMM): h_raw = x @ W1 (unscaled), warp per 2 nodes,
//                       W1 slice in registers.
// The two roles are data-independent and co-schedule across SMs, overlapping
// index streaming + atomics with x streaming + FMA.
__global__ void k_fused(const void* ei, const float* __restrict__ x,
                        const float* __restrict__ W1, int N, int E) {
    if (blockIdx.x < NB_CONV) {
        // ---- convert + degree role ----
        int t = blockIdx.x * blockDim.x + threadIdx.x;
        int e = t * 4;
        if (e >= E) return;
        int is64 = g_is64;
        int s[4], d[4];
        if (is64) {
            longlong2 sa = *(const longlong2*)((const long long*)ei + e);
            longlong2 sb = *(const longlong2*)((const long long*)ei + e + 2);
            longlong2 da = *(const longlong2*)((const long long*)ei + E + e);
            longlong2 db = *(const longlong2*)((const long long*)ei + E + e + 2);
            s[0] = (int)sa.x; s[1] = (int)sa.y; s[2] = (int)sb.x; s[3] = (int)sb.y;
            d[0] = (int)da.x; d[1] = (int)da.y; d[2] = (int)db.x; d[3] = (int)db.y;
        } else {
            int4 sv = *(const int4*)((const int*)ei + e);
            int4 dv = *(const int4*)((const int*)ei + E + e);
            s[0] = sv.x; s[1] = sv.y; s[2] = sv.z; s[3] = sv.w;
            d[0] = dv.x; d[1] = dv.y; d[2] = dv.z; d[3] = dv.w;
        }
        *(int4*)&g_edge[e]     = make_int4(s[0], d[0], s[1], d[1]);
        *(int4*)&g_edge[e + 2] = make_int4(s[2], d[2], s[3], d[3]);
#pragma unroll
        for (int i = 0; i < 4; i++) atomicAdd(&g_deg[d[i]], 1.0f);
        return;
    }

    // ---- gemm role: h_raw = x @ W1 ----
    int lane = threadIdx.x & 31;
    int cg   = lane >> 2;
    int fp   = lane & 3;

    float2 w2[16];
#pragma unroll
    for (int c = 0; c < 16; c++)
        w2[c] = *(const float2*)&W1[(cg * 16 + c) * 8 + fp * 2];

    int warp  = (((blockIdx.x - NB_CONV) * blockDim.x) + threadIdx.x) >> 5;
    int nwarp = (NB_GEMM * blockDim.x) >> 5;

    for (int n0 = warp * 2; n0 < N; n0 += nwarp * 2) {
        int n1 = n0 + 1;
        bool has1 = (n1 < N);

        const float4* xr0 = (const float4*)(x + (long long)n0 * 128);
        const float4* xr1 = (const float4*)(x + (long long)(has1 ? n1 : n0) * 128);

        float4 xa[4], xb[4];
#pragma unroll
        for (int i = 0; i < 4; i++) xa[i] = xr0[cg * 4 + i];
#pragma unroll
        for (int i = 0; i < 4; i++) xb[i] = xr1[cg * 4 + i];

        float a0 = 0.f, a1 = 0.f, b0 = 0.f, b1 = 0.f;
#pragma unroll
        for (int i = 0; i < 4; i++) {
            float2 wa = w2[i * 4 + 0], wb = w2[i * 4 + 1];
            float2 wc = w2[i * 4 + 2], wd = w2[i * 4 + 3];
            a0 = fmaf(xa[i].x, wa.x, a0); a1 = fmaf(xa[i].x, wa.y, a1);
            a0 = fmaf(xa[i].y, wb.x, a0); a1 = fmaf(xa[i].y, wb.y, a1);
            a0 = fmaf(xa[i].z, wc.x, a0); a1 = fmaf(xa[i].z, wc.y, a1);
            a0 = fmaf(xa[i].w, wd.x, a0); a1 = fmaf(xa[i].w, wd.y, a1);
            b0 = fmaf(xb[i].x, wa.x, b0); b1 = fmaf(xb[i].x, wa.y, b1);
            b0 = fmaf(xb[i].y, wb.x, b0); b1 = fmaf(xb[i].y, wb.y, b1);
            b0 = fmaf(xb[i].z, wc.x, b0); b1 = fmaf(xb[i].z, wc.y, b1);
            b0 = fmaf(xb[i].w, wd.x, b0); b1 = fmaf(xb[i].w, wd.y, b1);
        }
#pragma unroll
        for (int off = 16; off >= 4; off >>= 1) {
            a0 += __shfl_xor_sync(0xffffffffu, a0, off);
            a1 += __shfl_xor_sync(0xffffffffu, a1, off);
            b0 += __shfl_xor_sync(0xffffffffu, b0, off);
            b1 += __shfl_xor_sync(0xffffffffu, b1, off);
        }
        if (lane < 4) {
            *(float2*)&g_h[(long long)n0 * 8 + fp * 2] = make_float2(a0, a1);
            if (has1)
                *(float2*)&g_h[(long long)n1 * 8 + fp * 2] = make_float2(b0, b1);
        }
    }
}

// ---------------------------------------------------------------------------
// K2: dis = rsqrt(deg); h *= dis (in place); agg init = h_scaled (self term).
__global__ void k_scale(int N) {
    int n = blockIdx.x * blockDim.x + threadIdx.x;
    if (n >= N) return;
    float r = rsqrtf(g_deg[n]);
    g_dis[n] = r;
    float4* hp = (float4*)(g_h + (long long)n * 8);
    float4 u = hp[0], v = hp[1];
    u.x *= r; u.y *= r; u.z *= r; u.w *= r;
    v.x *= r; v.y *= r; v.z *= r; v.w *= r;
    hp[0] = u; hp[1] = v;
    float4* ap = (float4*)(g_agg + (long long)n * 8);
    ap[0] = u; ap[1] = v;
}

// ---------------------------------------------------------------------------
__device__ __forceinline__ void red_v4(float* p, float4 v) {
    asm volatile("red.global.add.v4.f32 [%0], {%1, %2, %3, %4};"
                 :: "l"(p), "f"(v.x), "f"(v.y), "f"(v.z), "f"(v.w) : "memory");
}

// Unweighted 8-dim edge scatter, 4 edges per thread:
//   dst_feat[d] += src_feat[s]   (normalization hoisted into node passes)
__device__ __forceinline__ void scatter8(const float* __restrict__ src_feat,
                                         float* __restrict__ dst_feat, int E) {
    int t = blockIdx.x * blockDim.x + threadIdx.x;
    int e = t * 4;
    if (e >= E) return;
    int4 p0 = *(const int4*)&g_edge[e];       // (s0,d0,s1,d1)
    int4 p1 = *(const int4*)&g_edge[e + 2];   // (s2,d2,s3,d3)

    const float4* h0 = (const float4*)(src_feat + (long long)p0.x * 8);
    const float4* h1 = (const float4*)(src_feat + (long long)p0.z * 8);
    const float4* h2 = (const float4*)(src_feat + (long long)p1.x * 8);
    const float4* h3 = (const float4*)(src_feat + (long long)p1.z * 8);
    float4 a0 = h0[0], a1 = h0[1];
    float4 b0 = h1[0], b1 = h1[1];
    float4 c0 = h2[0], c1 = h2[1];
    float4 e0 = h3[0], e1 = h3[1];

    float* o0 = dst_feat + (long long)p0.y * 8;
    float* o1 = dst_feat + (long long)p0.w * 8;
    float* o2 = dst_feat + (long long)p1.y * 8;
    float* o3 = dst_feat + (long long)p1.w * 8;
    red_v4(o0, a0); red_v4(o0 + 4, a1);
    red_v4(o1, b0); red_v4(o1 + 4, b1);
    red_v4(o2, c0); red_v4(o2 + 4, c1);
    red_v4(o3, e0); red_v4(o3 + 4, e1);
}

__global__ void k_sc1(int E) { scatter8(g_h, g_agg, E); }
__global__ void k_sc2(int E) { scatter8(g_r, g_agg2, E); }

// ---------------------------------------------------------------------------
// K3: r = relu(agg * dis + b1) * dis; agg2 init = r.
__global__ void k_mid(const float* __restrict__ b1, int N) {
    __shared__ float sb1[8];
    if (threadIdx.x < 8) sb1[threadIdx.x] = b1[threadIdx.x];
    __syncthreads();

    int n = blockIdx.x * blockDim.x + threadIdx.x;
    if (n >= N) return;

    float dis = g_dis[n];
    const float4* ap = (const float4*)(g_agg + (long long)n * 8);
    float4 u = ap[0], v = ap[1];
    float4 r0 = make_float4(fmaxf(fmaf(u.x, dis, sb1[0]), 0.0f) * dis,
                            fmaxf(fmaf(u.y, dis, sb1[1]), 0.0f) * dis,
                            fmaxf(fmaf(u.z, dis, sb1[2]), 0.0f) * dis,
                            fmaxf(fmaf(u.w, dis, sb1[3]), 0.0f) * dis);
    float4 r1 = make_float4(fmaxf(fmaf(v.x, dis, sb1[4]), 0.0f) * dis,
                            fmaxf(fmaf(v.y, dis, sb1[5]), 0.0f) * dis,
                            fmaxf(fmaf(v.z, dis, sb1[6]), 0.0f) * dis,
                            fmaxf(fmaf(v.w, dis, sb1[7]), 0.0f) * dis);
    float4* rp = (float4*)(g_r + (long long)n * 8);
    float4* a2 = (float4*)(g_agg2 + (long long)n * 8);
    rp[0] = r0; rp[1] = r1;
    a2[0] = r0; a2[1] = r1;
}

// ---------------------------------------------------------------------------
// K4: out = (agg2 * dis) @ W2 + b2
__global__ void k_out(const float* __restrict__ W2, const float* __restrict__ b2,
                      float* __restrict__ out, int N) {
    __shared__ float sW[8 * 16];
    __shared__ float sb2[16];
    if (threadIdx.x < 128) sW[threadIdx.x] = W2[threadIdx.x];
    if (threadIdx.x < 16) sb2[threadIdx.x] = b2[threadIdx.x];
    __syncthreads();

    int n = blockIdx.x * blockDim.x + threadIdx.x;
    if (n >= N) return;

    float dis = g_dis[n];
    const float4* ap = (const float4*)(g_agg2 + (long long)n * 8);
    float4 u = ap[0], v = ap[1];
    float a[8] = {u.x * dis, u.y * dis, u.z * dis, u.w * dis,
                  v.x * dis, v.y * dis, v.z * dis, v.w * dis};

    float o[16];
#pragma unroll
    for (int j = 0; j < 16; j++) o[j] = sb2[j];
#pragma unroll
    for (int k = 0; k < 8; k++) {
        float ak = a[k];
#pragma unroll
        for (int j = 0; j < 16; j++) o[j] = fmaf(ak, sW[k * 16 + j], o[j]);
    }

    float4* op = (float4*)(out + (long long)n * 16);
#pragma unroll
    for (int q = 0; q < 4; q++)
        op[q] = make_float4(o[q * 4], o[q * 4 + 1], o[q * 4 + 2], o[q * 4 + 3]);
}

// ---------------------------------------------------------------------------
extern "C" void kernel_launch(void* const* d_in, const int* in_sizes, int n_in,
                              void* d_out, int out_size) {
    const float* x   = (const float*)d_in[0];
    const void*  ei  = d_in[1];
    const float* W1  = (const float*)d_in[2];
    const float* b1  = (const float*)d_in[3];
    const float* W2  = (const float*)d_in[4];
    const float* b2  = (const float*)d_in[5];
    float* out = (float*)d_out;

    int N = in_sizes[0] / 128;
    int E = in_sizes[1] / 2;

    const int T = 256;
    int nb_N  = (N + T - 1) / T;
    int nb_E4 = ((E + 3) / 4 + T - 1) / T;

    k_detect<<<1, 32>>>(ei, N);
    k_init<<<nb_N, T>>>(N);
    k_fused<<<NB_CONV + NB_GEMM, T>>>(ei, x, W1, N, E);
    k_scale<<<nb_N, T>>>(N);
    k_sc1<<<nb_E4, T>>>(E);
    k_mid<<<nb_N, T>>>(b1, N);
    k_sc2<<<nb_E4, T>>>(E);
    k_out<<<nb_N, T>>>(W2, b2, out, N);
}

// round 12
// speedup vs baseline: 1.5126x; 1.1542x over previous
#include <cuda_runtime.h>

// Problem constants (fixed by the dataset): N=200000, E=6400000, F: 128 -> 8 -> 16
#define NMAX 200000
#define EMAX 6400000

// Scratch (no cudaMalloc allowed)
__device__ float g_deg[NMAX];         // degree (float counts)
__device__ float g_dis[NMAX];         // deg^-1/2
__device__ float g_h[NMAX * 8];       // (x @ W1) * dis[src]   (pre-scaled)
__device__ float g_agg[NMAX * 8];     // layer-1 unweighted aggregation
__device__ float g_r[NMAX * 8];       // relu(...) * dis[src]  (pre-scaled)
__device__ float g_agg2[NMAX * 8];    // layer-2 unweighted aggregation
__device__ int2  g_edge[EMAX];        // packed (src, dst) int32
__device__ int   g_is64;              // edge_index dtype flag

// ---------------------------------------------------------------------------
// K0: detect whether edge_index is int64 or int32.
__global__ void k_detect(const void* ei, int N) {
    if (threadIdx.x == 0 && blockIdx.x == 0) {
        const long long* p = (const long long*)ei;
        int is64 = 1;
#pragma unroll
        for (int i = 0; i < 8; i++) {
            long long v = p[i];
            if (v < 0 || v >= (long long)N) is64 = 0;
        }
        g_is64 = is64;
    }
}

__global__ void k_deg_init(int N) {
    int i = blockIdx.x * blockDim.x + threadIdx.x;
    if (i < N) g_deg[i] = 1.0f;   // self-loop
}

// ---------------------------------------------------------------------------
// K1: convert indices to packed int2 (2 edges/thread) + degree scatter.
__global__ void k_convert_deg(const void* ei, int E) {
    int t = blockIdx.x * blockDim.x + threadIdx.x;   // over E/2 pairs
    int e = t * 2;
    if (e >= E) return;
    int is64 = g_is64;
    int s0, d0, s1, d1;
    if (is64) {
        longlong2 sv = ((const longlong2*)ei)[t];
        longlong2 dv = *(const longlong2*)((const long long*)ei + E + e);
        s0 = (int)sv.x; s1 = (int)sv.y;
        d0 = (int)dv.x; d1 = (int)dv.y;
    } else {
        int2 sv = *(const int2*)((const int*)ei + e);
        int2 dv = *(const int2*)((const int*)ei + E + e);
        s0 = sv.x; s1 = sv.y;
        d0 = dv.x; d1 = dv.y;
    }
    *(int4*)&g_edge[e] = make_int4(s0, d0, s1, d1);
    atomicAdd(&g_deg[d0], 1.0f);
    atomicAdd(&g_deg[d1], 1.0f);
}

// ---------------------------------------------------------------------------
// K2: h_scaled = (x @ W1) * dis. Warp per 2 nodes, grid-stride. W in regs.
// Fused: dis = rsqrt(deg) stored once, agg init = h_scaled (self-loop term).
__global__ void k_gemm1(const float* __restrict__ x, const float* __restrict__ W1, int N) {
    int lane = threadIdx.x & 31;
    int cg   = lane >> 2;
    int fp   = lane & 3;

    float2 w2[16];
#pragma unroll
    for (int c = 0; c < 16; c++)
        w2[c] = *(const float2*)&W1[(cg * 16 + c) * 8 + fp * 2];

    int warp  = (blockIdx.x * blockDim.x + threadIdx.x) >> 5;
    int nwarp = (gridDim.x * blockDim.x) >> 5;

    for (int n0 = warp * 2; n0 < N; n0 += nwarp * 2) {
        int n1 = n0 + 1;
        bool has1 = (n1 < N);

        const float4* xr0 = (const float4*)(x + (long long)n0 * 128);
        const float4* xr1 = (const float4*)(x + (long long)(has1 ? n1 : n0) * 128);

        float4 xa[4], xb[4];
#pragma unroll
        for (int i = 0; i < 4; i++) xa[i] = xr0[cg * 4 + i];
#pragma unroll
        for (int i = 0; i < 4; i++) xb[i] = xr1[cg * 4 + i];

        float a0 = 0.f, a1 = 0.f, b0 = 0.f, b1 = 0.f;
#pragma unroll
        for (int i = 0; i < 4; i++) {
            float2 wa = w2[i * 4 + 0], wb = w2[i * 4 + 1];
            float2 wc = w2[i * 4 + 2], wd = w2[i * 4 + 3];
            a0 = fmaf(xa[i].x, wa.x, a0); a1 = fmaf(xa[i].x, wa.y, a1);
            a0 = fmaf(xa[i].y, wb.x, a0); a1 = fmaf(xa[i].y, wb.y, a1);
            a0 = fmaf(xa[i].z, wc.x, a0); a1 = fmaf(xa[i].z, wc.y, a1);
            a0 = fmaf(xa[i].w, wd.x, a0); a1 = fmaf(xa[i].w, wd.y, a1);
            b0 = fmaf(xb[i].x, wa.x, b0); b1 = fmaf(xb[i].x, wa.y, b1);
            b0 = fmaf(xb[i].y, wb.x, b0); b1 = fmaf(xb[i].y, wb.y, b1);
            b0 = fmaf(xb[i].z, wc.x, b0); b1 = fmaf(xb[i].z, wc.y, b1);
            b0 = fmaf(xb[i].w, wd.x, b0); b1 = fmaf(xb[i].w, wd.y, b1);
        }
#pragma unroll
        for (int off = 16; off >= 4; off >>= 1) {
            a0 += __shfl_xor_sync(0xffffffffu, a0, off);
            a1 += __shfl_xor_sync(0xffffffffu, a1, off);
            b0 += __shfl_xor_sync(0xffffffffu, b0, off);
            b1 += __shfl_xor_sync(0xffffffffu, b1, off);
        }

        float r = 0.0f;
        if (lane < 2) {
            int nn = n0 + lane;
            if (nn < N) {
                r = rsqrtf(g_deg[nn]);
                g_dis[nn] = r;
            }
        }
        float r0 = __shfl_sync(0xffffffffu, r, 0);
        float r1 = __shfl_sync(0xffffffffu, r, 1);

        if (lane < 4) {
            float2 v0 = make_float2(a0 * r0, a1 * r0);
            *(float2*)&g_h[(long long)n0 * 8 + fp * 2]   = v0;
            *(float2*)&g_agg[(long long)n0 * 8 + fp * 2] = v0;
            if (has1) {
                float2 v1 = make_float2(b0 * r1, b1 * r1);
                *(float2*)&g_h[(long long)n1 * 8 + fp * 2]   = v1;
                *(float2*)&g_agg[(long long)n1 * 8 + fp * 2] = v1;
            }
        }
    }
}

// ---------------------------------------------------------------------------
__device__ __forceinline__ void red_v4(float* p, float4 v) {
    asm volatile("red.global.add.v4.f32 [%0], {%1, %2, %3, %4};"
                 :: "l"(p), "f"(v.x), "f"(v.y), "f"(v.z), "f"(v.w) : "memory");
}

// Unweighted 8-dim edge scatter, PAIR-COOPERATIVE:
// two adjacent lanes share one edge; each lane handles one 16B half of the
// 32B feature row, so the pair's gather (and RED) requests land in the SAME
// 32B sector and coalesce into one wavefront. 2 edges per lane-pair for MLP.
__device__ __forceinline__ void scatter8(const float* __restrict__ src_feat,
                                         float* __restrict__ dst_feat, int E) {
    int t    = blockIdx.x * blockDim.x + threadIdx.x;
    int half = t & 1;            // which 16B half of the row
    int e0   = (t >> 1) * 2;     // first of 2 edges for this pair
    if (e0 >= E) return;

    int4 sd = *(const int4*)&g_edge[e0];   // (s0,d0,s1,d1); pair lanes dedup

    const float4 a = *(const float4*)(src_feat + (long long)sd.x * 8 + half * 4);
    bool has1 = (e0 + 1 < E);
    float4 b;
    if (has1) b = *(const float4*)(src_feat + (long long)sd.z * 8 + half * 4);

    red_v4(dst_feat + (long long)sd.y * 8 + half * 4, a);
    if (has1) red_v4(dst_feat + (long long)sd.w * 8 + half * 4, b);
}

__global__ void k_sc1(int E) { scatter8(g_h, g_agg, E); }
__global__ void k_sc2(int E) { scatter8(g_r, g_agg2, E); }

// ---------------------------------------------------------------------------
// K3: r = relu(agg * dis + b1) * dis; agg2 init = r.
__global__ void k_mid(const float* __restrict__ b1, int N) {
    __shared__ float sb1[8];
    if (threadIdx.x < 8) sb1[threadIdx.x] = b1[threadIdx.x];
    __syncthreads();

    int n = blockIdx.x * blockDim.x + threadIdx.x;
    if (n >= N) return;

    float dis = g_dis[n];
    const float4* ap = (const float4*)(g_agg + (long long)n * 8);
    float4 u = ap[0], v = ap[1];
    float4 r0 = make_float4(fmaxf(fmaf(u.x, dis, sb1[0]), 0.0f) * dis,
                            fmaxf(fmaf(u.y, dis, sb1[1]), 0.0f) * dis,
                            fmaxf(fmaf(u.z, dis, sb1[2]), 0.0f) * dis,
                            fmaxf(fmaf(u.w, dis, sb1[3]), 0.0f) * dis);
    float4 r1 = make_float4(fmaxf(fmaf(v.x, dis, sb1[4]), 0.0f) * dis,
                            fmaxf(fmaf(v.y, dis, sb1[5]), 0.0f) * dis,
                            fmaxf(fmaf(v.z, dis, sb1[6]), 0.0f) * dis,
                            fmaxf(fmaf(v.w, dis, sb1[7]), 0.0f) * dis);
    float4* rp = (float4*)(g_r + (long long)n * 8);
    float4* a2 = (float4*)(g_agg2 + (long long)n * 8);
    rp[0] = r0; rp[1] = r1;
    a2[0] = r0; a2[1] = r1;
}

// ---------------------------------------------------------------------------
// K4: out = (agg2 * dis) @ W2 + b2
__global__ void k_out(const float* __restrict__ W2, const float* __restrict__ b2,
                      float* __restrict__ out, int N) {
    __shared__ float sW[8 * 16];
    __shared__ float sb2[16];
    if (threadIdx.x < 128) sW[threadIdx.x] = W2[threadIdx.x];
    if (threadIdx.x < 16) sb2[threadIdx.x] = b2[threadIdx.x];
    __syncthreads();

    int n = blockIdx.x * blockDim.x + threadIdx.x;
    if (n >= N) return;

    float dis = g_dis[n];
    const float4* ap = (const float4*)(g_agg2 + (long long)n * 8);
    float4 u = ap[0], v = ap[1];
    float a[8] = {u.x * dis, u.y * dis, u.z * dis, u.w * dis,
                  v.x * dis, v.y * dis, v.z * dis, v.w * dis};

    float o[16];
#pragma unroll
    for (int j = 0; j < 16; j++) o[j] = sb2[j];
#pragma unroll
    for (int k = 0; k < 8; k++) {
        float ak = a[k];
#pragma unroll
        for (int j = 0; j < 16; j++) o[j] = fmaf(ak, sW[k * 16 + j], o[j]);
    }

    float4* op = (float4*)(out + (long long)n * 16);
#pragma unroll
    for (int q = 0; q < 4; q++)
        op[q] = make_float4(o[q * 4], o[q * 4 + 1], o[q * 4 + 2], o[q * 4 + 3]);
}

// ---------------------------------------------------------------------------
extern "C" void kernel_launch(void* const* d_in, const int* in_sizes, int n_in,
                              void* d_out, int out_size) {
    const float* x   = (const float*)d_in[0];
    const void*  ei  = d_in[1];
    const float* W1  = (const float*)d_in[2];
    const float* b1  = (const float*)d_in[3];
    const float* W2  = (const float*)d_in[4];
    const float* b2  = (const float*)d_in[5];
    float* out = (float*)d_out;

    int N = in_sizes[0] / 128;
    int E = in_sizes[1] / 2;

    const int T = 256;
    int nb_N  = (N + T - 1) / T;
    int nb_E2 = (E / 2 + T - 1) / T;
    // scatter: 2 threads per 2 edges -> E threads total
    int nb_SC = (E + T - 1) / T;

    k_detect<<<1, 32>>>(ei, N);
    k_deg_init<<<nb_N, T>>>(N);
    k_convert_deg<<<nb_E2, T>>>(ei, E);
    k_gemm1<<<1184, T>>>(x, W1, N);
    k_sc1<<<nb_SC, T>>>(E);
    k_mid<<<nb_N, T>>>(b1, N);
    k_sc2<<<nb_SC, T>>>(E);
    k_out<<<nb_N, T>>>(W2, b2, out, N);
}